// round 16
// baseline (speedup 1.0000x reference)
#include <cuda_runtime.h>
#include <math.h>

// Problem constants (fixed by dataset)
#define NSAMP 8192
#define NND  (NSAMP * 64)        // 524288 (giant row length)
#define NPAIR 136                // 16*17/2 gram pairs
#define GTILE_COLS 512           // cols per gram block
#define GNTILE 1024              // 524288 / 512

typedef unsigned long long ull;

// ---------------- device globals (scratch, statically allocated) ----------------
__device__ float g_partials[NPAIR][GNTILE];
__device__ float g_gram[NPAIR];
__device__ ull   g_coefQd[256];  // dup-packed (v,v) coefs
__device__ ull   g_coefKd[256];
__device__ float g_firstQ[16];
__device__ float g_firstK[16];
__device__ float g_uQ[64];
__device__ float g_uK[64];
__device__ float g_u2[2];        // ||u||^2 (dims 1..63) for q,k

__device__ __forceinline__ float wreduce(float v) {
#pragma unroll
    for (int o = 16; o; o >>= 1) v += __shfl_xor_sync(0xffffffffu, v, o);
    return v;
}

__device__ __forceinline__ ull fma2(ull a, ull b, ull c) {
    ull d; asm("fma.rn.f32x2 %0, %1, %2, %3;" : "=l"(d) : "l"(a), "l"(b), "l"(c));
    return d;
}
__device__ __forceinline__ ull mul2(ull a, ull b) {
    ull d; asm("mul.rn.f32x2 %0, %1, %2;" : "=l"(d) : "l"(a), "l"(b));
    return d;
}
__device__ __forceinline__ ull pack2(float lo, float hi) {
    ull d; asm("mov.b64 %0, {%1, %2};" : "=l"(d) : "f"(lo), "f"(hi));
    return d;
}
__device__ __forceinline__ void unpack2(ull v, float& lo, float& hi) {
    asm("mov.b64 {%0, %1}, %2;" : "=f"(lo), "=f"(hi) : "l"(v));
}

// ---------------- Kernel 1: Gram partials, warp-per-4x4-block, float4 LDS ----------------
extern "C" __global__ __launch_bounds__(320)
void gram_kernel(const float* __restrict__ H) {
    __shared__ float gt[16 * GTILE_COLS];   // 32KB
    const int b = blockIdx.x;
    const int tid = threadIdx.x;

    const float4* H4 = reinterpret_cast<const float4*>(H);
    for (int i = tid; i < 16 * (GTILE_COLS / 4); i += 320) {
        int s = i >> 7;
        int c4 = i & 127;
        reinterpret_cast<float4*>(gt + s * GTILE_COLS)[c4] =
            H4[(size_t)s * (NND / 4) + (size_t)b * (GTILE_COLS / 4) + c4];
    }
    __syncthreads();

    const int w = tid >> 5, lane = tid & 31;
    const int bi_arr[10] = {0, 1, 1, 2, 2, 2, 3, 3, 3, 3};
    const int bj_arr[10] = {0, 0, 1, 0, 1, 2, 0, 1, 2, 3};
    const int bi = bi_arr[w], bj = bj_arr[w];

    const float4* A4 = reinterpret_cast<const float4*>(gt + (bi * 4) * GTILE_COLS);
    const float4* B4 = reinterpret_cast<const float4*>(gt + (bj * 4) * GTILE_COLS);
    const int R = GTILE_COLS / 4;   // 128 float4 per row
    float acc[16];
#pragma unroll
    for (int i = 0; i < 16; i++) acc[i] = 0.f;

#define ACC4(i, j, av, bv) acc[(i)*4+(j)] = fmaf(av.x, bv.x, fmaf(av.y, bv.y, fmaf(av.z, bv.z, fmaf(av.w, bv.w, acc[(i)*4+(j)]))));
#pragma unroll
    for (int c = 0; c < 4; c++) {
        int idx = c * 32 + lane;
        float4 a0 = A4[idx], a1 = A4[idx + R], a2 = A4[idx + 2 * R], a3 = A4[idx + 3 * R];
        float4 b0 = B4[idx], b1 = B4[idx + R], b2 = B4[idx + 2 * R], b3 = B4[idx + 3 * R];
        ACC4(0, 0, a0, b0)  ACC4(0, 1, a0, b1)  ACC4(0, 2, a0, b2)  ACC4(0, 3, a0, b3)
        ACC4(1, 0, a1, b0)  ACC4(1, 1, a1, b1)  ACC4(1, 2, a1, b2)  ACC4(1, 3, a1, b3)
        ACC4(2, 0, a2, b0)  ACC4(2, 1, a2, b1)  ACC4(2, 2, a2, b2)  ACC4(2, 3, a2, b3)
        ACC4(3, 0, a3, b0)  ACC4(3, 1, a3, b1)  ACC4(3, 2, a3, b2)  ACC4(3, 3, a3, b3)
    }
#undef ACC4

#pragma unroll
    for (int ki = 0; ki < 4; ki++) {
#pragma unroll
        for (int kj = 0; kj < 4; kj++) {
            float v = wreduce(acc[ki * 4 + kj]);
            int s2 = bi * 4 + ki, s1 = bj * 4 + kj;
            if (lane == 0 && s1 <= s2)
                g_partials[(s2 * (s2 + 1)) / 2 + s1][b] = v;
        }
    }
}

// ---------------- Kernel 1b: parallel deterministic reduction of partials ----------------
extern "C" __global__ __launch_bounds__(256)
void reduce_kernel() {
    __shared__ float red[8];
    const int p = blockIdx.x;
    const int tid = threadIdx.x;
    const int w = tid >> 5, lane = tid & 31;
    float acc = 0.f;
    for (int k = tid; k < GNTILE; k += 256) acc += g_partials[p][k];
    acc = wreduce(acc);
    if (lane == 0) red[w] = acc;
    __syncthreads();
    if (w == 0) {
        float v = (lane < 8) ? red[lane] : 0.f;
        v = wreduce(v);
        if (lane == 0) g_gram[p] = v;
    }
}

// ---------------- Kernel 2: finalize small algebra ----------------
extern "C" __global__ __launch_bounds__(256, 1)
void finalize_kernel(const float* __restrict__ H,
                     const float* __restrict__ wq, const float* __restrict__ wk,
                     const float* __restrict__ bq, const float* __restrict__ bk,
                     const float* __restrict__ cin) {
    __shared__ float Gf[NPAIR];
    __shared__ float h0[16];
    __shared__ float scale[16];
    __shared__ float ubv[2], bnv[2];

    const int tid = threadIdx.x;
    const float cval = cin[0];
    const float Kv = 1.f / cval;
    const float sK = sqrtf(Kv);
    const float onep = 1.f + 1e-7f;

    if (tid < NPAIR) Gf[tid] = g_gram[tid];
    if (tid >= NPAIR && tid < NPAIR + 16) h0[tid - NPAIR] = H[(size_t)(tid - NPAIR) * NND];
    __syncthreads();

    auto GX = [&](int s1, int s2) -> float {
        int a = min(s1, s2), b = max(s1, s2);
        return Gf[(b * (b + 1)) / 2 + a] - h0[s1] * h0[s2];
    };

    if (tid < 16) {
        int s = tid;
        float yn = fmaxf(sqrtf(GX(s, s)), 1e-15f);
        float th = fmaxf(h0[s] / sK, onep);
        float ar = logf(th + sqrtf(fmaxf(th * th - 1.f, 1e-7f)));
        scale[s] = sK * ar / yn;
    }
    __syncthreads();

    if (tid < 32) {
        int r = tid & 15;
        const float* W = (tid < 16) ? wq : wk;
        ull* coefd = (tid < 16) ? g_coefQd : g_coefKd;
        float* first = (tid < 16) ? g_firstQ : g_firstK;
        float Wp[16];
#pragma unroll
        for (int s = 0; s < 16; s++) Wp[s] = W[r * 16 + s] * scale[s];
        float xn2 = 0.f;
        for (int s = 0; s < 16; s++)
            for (int s2 = 0; s2 < 16; s2++)
                xn2 = fmaf(Wp[s] * Wp[s2], GX(s, s2), xn2);
        float xn = fmaxf(sqrtf(xn2), 1e-15f);
        float th = xn / sK;
        float cA = sK * sinhf(th) / xn;
        first[r] = sK * coshf(th);
#pragma unroll
        for (int s = 0; s < 16; s++) {
            float v = cA * Wp[s];
            coefd[r * 16 + s] = pack2(v, v);
        }
    }
    if (tid == 32 || tid == 33) {
        const float* b = (tid == 32) ? bq : bk;
        float s2 = 0.f;
        for (int j = 1; j < 64; j++) s2 += b[j] * b[j];
        float bn = fmaxf(sqrtf(s2), 1e-15f);
        float tb = fmaxf(b[0] / sK, onep);
        float ub = sK * logf(tb + sqrtf(fmaxf(tb * tb - 1.f, 1e-7f)));
        ubv[tid - 32] = ub;
        bnv[tid - 32] = bn;
        g_u2[tid - 32] = ub * ub;     // ||u||^2 = ub^2 since u = ub * y/||y||
    }
    __syncthreads();
    if (tid < 128) {
        int j = tid & 63;
        if (tid < 64) g_uQ[j] = (j == 0) ? 0.f : ubv[0] * bq[j] / bnv[0];
        else          g_uK[j] = (j == 0) ? 0.f : ubv[1] * bk[j] / bnv[1];
    }
}

// ---------------- Kernel 3: fused main, half-group CTAs (256 thr, 3 CTAs/SM) ----------------
extern "C" __global__ __launch_bounds__(256, 3)
void main_kernel(const float* __restrict__ H, const float* __restrict__ mask,
                 const float* __restrict__ ain, const float* __restrict__ cin,
                 float* __restrict__ out) {
    extern __shared__ float smem[];
    float* qm   = smem;                    // 8*1024
    float* km   = qm + 8192;               // 8*1024
    ull*   cQd  = (ull*)(km + 8192);       // 128 ull (this half's packed q coefs)
    ull*   cKd  = cQd + 128;               // 128 ull
    float* fQh  = (float*)(cKd + 128);     // 8
    float* fKh  = fQh + 8;                 // 8
    float* uq   = fKh + 8;                 // 64
    float* uk   = uq + 64;                 // 64
    float* sbuf = uk + 64;                 // 8*136
    float* zfac = sbuf + 8 * 136;          // 8*16
    float* wfac = zfac + 128;              // 8*16
    float* wsS  = wfac + 128;              // 8*16
    float* maskS= wsS + 128;               // 136
    float* firsts = (float*)cQd;           // OVERLAY (256 floats; coefs dead after phase 2)

    const int g = blockIdx.x >> 1;
    const int half = blockIdx.x & 1;
    const int tid = threadIdx.x;
    const int lane = tid & 31, warp = tid >> 5;
    const float cval = __ldg(cin);
    const float aval = __ldg(ain);
    const float Kv = 1.f / cval;
    const float sK = sqrtf(Kv);
    const float onep = 1.f + 1e-7f;

    if (tid < 128) cQd[tid] = g_coefQd[half * 128 + tid];
    else           cKd[tid - 128] = g_coefKd[half * 128 + (tid - 128)];
    if (tid < 8)   { fQh[tid] = g_firstQ[half * 8 + tid]; fKh[tid] = g_firstK[half * 8 + tid]; }
    if (tid >= 8 && tid < 72)   uq[tid - 8] = g_uQ[tid - 8];
    if (tid >= 72 && tid < 136) uk[tid - 72] = g_uK[tid - 72];
    if (tid >= 120 && tid < 256) maskS[tid - 120] = __ldg(mask + (tid - 120));
    __syncthreads();

    // ---- phase 2: 16x16 mix -> 8 q,k r-rows (packed f32x2, pre-dup coefs) ----
    {
        const float2* H2 = reinterpret_cast<const float2*>(H);
        float2* q2 = reinterpret_cast<float2*>(qm);
        float2* k2 = reinterpret_cast<float2*>(km);
#pragma unroll
        for (int cp = 0; cp < 2; cp++) {
            const int col = tid + cp * 256;     // float2 column in 0..511
            ull tv[16];
#pragma unroll
            for (int s = 0; s < 16; s++) {
                float2 v = __ldg(&H2[(size_t)(s * 512 + g) * 512 + col]);
                tv[s] = pack2(v.x, v.y);
            }
#pragma unroll
            for (int rl = 0; rl < 8; rl++) {
                const ulonglong2* cq2 = reinterpret_cast<const ulonglong2*>(cQd + rl * 16);
                const ulonglong2* ck2 = reinterpret_cast<const ulonglong2*>(cKd + rl * 16);
                ull aq = 0ull, ak = 0ull;
#pragma unroll
                for (int s2 = 0; s2 < 8; s2++) {
                    ulonglong2 cq = cq2[s2], ck = ck2[s2];
                    aq = fma2(cq.x, tv[2 * s2],     aq);
                    aq = fma2(cq.y, tv[2 * s2 + 1], aq);
                    ak = fma2(ck.x, tv[2 * s2],     ak);
                    ak = fma2(ck.y, tv[2 * s2 + 1], ak);
                }
                float qlo, qhi, klo, khi;
                unpack2(aq, qlo, qhi);
                unpack2(ak, klo, khi);
                if (g == 0 && col == 0) { qlo = fQh[rl]; klo = fKh[rl]; }  // expmap0 first column
                q2[rl * 512 + col] = make_float2(qlo, qhi);
                k2[rl * 512 + col] = make_float2(klo, khi);
            }
        }
    }
    __syncthreads();

    // ---- phase 3: mobius_add(b) + proj, thread-per-row, packed f32x2, closed form ----
    {
        const bool isq = tid < 128;
        float* X = isq ? qm : km;
        const float4* U4 = reinterpret_cast<const float4*>(isq ? uq : uk);
        const float u2 = isq ? g_u2[0] : g_u2[1];
        const int rloc = tid & 127;             // local sample (rloc>>4), tt (rloc&15)
        float* row = X + (rloc >> 4) * 1024 + (rloc & 15) * 64;
        float4* row4 = reinterpret_cast<float4*>(row);

        float x0 = 0.f;
        ull accY0 = 0ull, accY1 = 0ull, accD0 = 0ull, accD1 = 0ull;
#pragma unroll
        for (int jp = 0; jp < 16; jp++) {
            int p = (jp + lane) & 15;
            float4 xv = row4[p];
            float4 uv = U4[p];
            if (p == 0) x0 = xv.x;
            ull xa = pack2(xv.x, xv.y), xb = pack2(xv.z, xv.w);
            ull ua = pack2(uv.x, uv.y), ub = pack2(uv.z, uv.w);
            accY0 = fma2(xa, xa, accY0);
            accY1 = fma2(xb, xb, accY1);
            accD0 = fma2(xa, ua, accD0);
            accD1 = fma2(xb, ub, accD1);
        }
        float y0l, y0h, y1l, y1h, d0l, d0h, d1l, d1h;
        unpack2(accY0, y0l, y0h); unpack2(accY1, y1l, y1h);
        unpack2(accD0, d0l, d0h); unpack2(accD1, d1l, d1h);
        float yn2 = ((y0l + y0h) + (y1l + y1h)) - x0 * x0;   // exclude dim0
        float du  = (d0l + d0h) + (d1l + d1h);               // U[0]=0 -> exact

        float yn = fmaxf(sqrtf(fmaxf(yn2, 0.f)), 1e-15f);
        float alpha = du / (yn * sK);
        float fac = alpha * (sK - x0) / yn;
        float ux = du - fac * yn2;
        float first = ux / fmaxf(x0, 1e-7f);
        float w2 = fmaf(fac * fac, yn2, fmaf(-2.f * fac, du, u2));
        float md = fmaxf(w2 - first * first, 1e-7f);
        float nrm = fminf(sqrtf(md), 1e6f);
        float th = fmaxf(nrm / sK, 1e-15f);
        float ch = coshf(th);
        float shn = sinhf(th) / th;
        float A = fmaf(-shn, fac, ch);
        float B = shn;
        float r2 = fmaf(A * A, yn2, fmaf(2.f * A * B, du, B * B * u2));
        float o0 = sqrtf(fmaxf(Kv + r2, 1e-7f));

        const ull A2 = pack2(A, A), B2 = pack2(B, B);
#pragma unroll
        for (int jp = 0; jp < 16; jp++) {
            int p = (jp + lane) & 15;
            float4 xv = row4[p];
            float4 uv = U4[p];
            ull xa = pack2(xv.x, xv.y), xb = pack2(xv.z, xv.w);
            ull ua = pack2(uv.x, uv.y), ub = pack2(uv.z, uv.w);
            ull ra = fma2(A2, xa, mul2(B2, ua));
            ull rb = fma2(A2, xb, mul2(B2, ub));
            float4 rv;
            unpack2(ra, rv.x, rv.y);
            unpack2(rb, rv.z, rv.w);
            row4[p] = rv;
        }
        row[0] = o0;
        firsts[(isq ? 0 : 128) + rloc] = o0;     // overlay onto dead coef region
    }
    __syncthreads();

    // ---- phase 4: attention, warp per sample (8 warps, 8 samples) ----
    {
        const int smg = half * 8 + warp;         // global sample index
        const int brv = ((lane & 1) << 3) | ((lane & 2) << 1) | ((lane & 4) >> 1) | ((lane & 8) >> 3);
        const int brv3 = ((lane & 1) << 2) | (lane & 2) | ((lane & 4) >> 2);   // rev of low 3 bits
        const float2* hv2 = reinterpret_cast<const float2*>(H) + (size_t)(smg * 512 + g) * 512;

        // ---- dots: register-tiled 4x4 pair blocks, q hoisted out of bj loop ----
        {
            const float2* q2 = reinterpret_cast<const float2*>(qm + warp * 1024);
            const float2* k2 = reinterpret_cast<const float2*>(km + warp * 1024);
            const int pi = brv >> 2, pj = brv & 3;

            for (int bi = 0; bi < 4; bi++) {
                float2 qv[4];
#pragma unroll
                for (int i = 0; i < 4; i++) qv[i] = q2[(bi * 4 + i) * 32 + lane];
                for (int bj = 0; bj <= bi; bj++) {
                    float2 kv[4];
#pragma unroll
                    for (int j = 0; j < 4; j++) kv[j] = k2[(bj * 4 + j) * 32 + lane];
                    float acc[16];
#pragma unroll
                    for (int i = 0; i < 4; i++)
#pragma unroll
                        for (int j = 0; j < 4; j++)
                            acc[i * 4 + j] = fmaf(qv[i].x, kv[j].x, qv[i].y * kv[j].y);
#pragma unroll
                    for (int step = 0; step < 4; step++) {
                        const int mm = 1 << step;
                        const int h = 8 >> step;
                        const bool hi = (lane & mm) != 0;
#pragma unroll
                        for (int i = 0; i < h; i++) {
                            float sent = hi ? acc[i] : acc[i + h];
                            float recv = __shfl_xor_sync(0xffffffffu, sent, mm);
                            acc[i] = (hi ? acc[i + h] : acc[i]) + recv;
                        }
                    }
                    float S = acc[0] + __shfl_xor_sync(0xffffffffu, acc[0], 16);
                    int mt = bi * 4 + pi, nt = bj * 4 + pj;
                    if (lane < 16 && nt <= mt) {
                        int e = ((mt * (mt + 1)) >> 1) + nt;
                        float q0 = firsts[warp * 16 + mt];
                        float k0 = firsts[128 + warp * 16 + nt];
                        float mdot = S - 2.f * q0 * k0;
                        float thv = fmaxf(-mdot * cval, onep);
                        float ar = __logf(thv + sqrtf(fmaxf(thv * thv - 1.f, 1e-7f)));
                        float sq = fminf(Kv * ar * ar, 50.f);
                        sbuf[warp * 136 + e] = __expf(fmaf(-aval, sq, maskS[e] - cval));
                    }
                }
            }
        }
        __syncwarp();

        // ---- lorenz factors from v16 (kept in regs through scatter) ----
        float2 v16[16];
#pragma unroll
        for (int n = 0; n < 16; n++) v16[n] = __ldg(&hv2[n * 32 + lane]);
        {
            float h0b = 0.f;
            if (lane < 16) h0b = __ldg(H + (size_t)(smg * 512 + g) * 1024 + brv * 64);
            float acc[16];
#pragma unroll
            for (int n = 0; n < 16; n++)
                acc[n] = fmaf(v16[n].x, v16[n].x, v16[n].y * v16[n].y);
#pragma unroll
            for (int step = 0; step < 4; step++) {
                const int mm = 1 << step;
                const int h = 8 >> step;
                const bool hi = (lane & mm) != 0;
#pragma unroll
                for (int i = 0; i < h; i++) {
                    float sent = hi ? acc[i] : acc[i + h];
                    float recv = __shfl_xor_sync(0xffffffffu, sent, mm);
                    acc[i] = (hi ? acc[i + h] : acc[i]) + recv;
                }
            }
            float S = acc[0] + __shfl_xor_sync(0xffffffffu, acc[0], 16);
            if (lane < 16) {
                float iv = 1.f / h0b;
                float svn = (S - h0b * h0b) * iv * iv;
                zfac[warp * 16 + brv] = iv;
                wfac[warp * 16 + brv] = rsqrtf(1.f - fminf(svn, 0.9f));
            }
        }
        __syncwarp();

        // ---- ssum per m, split across 32 lanes (lane m: first half, lane m+16: rest) ----
        {
            const int m = lane & 15;
            const int base = (m * (m + 1)) >> 1;
            const int cnt = m + 1;
            const int h1 = (cnt + 1) >> 1;
            const int lo = (lane < 16) ? 0 : h1;
            const int hi = (lane < 16) ? h1 : cnt;
            float acc = 0.f;
            for (int n = lo; n < hi; n++) acc += sbuf[warp * 136 + base + n];
            acc += __shfl_xor_sync(0xffffffffu, acc, 16);
            if (lane < 16) {
                float f = wfac[warp * 16 + m] / acc;    // lamb / ssum
                wfac[warp * 16 + m] = f;
                zfac[warp * 16 + m] = f * zfac[warp * 16 + m];
            }
        }
        __syncwarp();

        // ---- wsum + coefficient matrix in place (lane m handles row m) ----
        if (lane < 16) {
            float* sb = sbuf + warp * 136;
            int base = (lane * (lane + 1)) >> 1;
            float acc = 0.f;
            for (int n = 0; n <= lane; n++) {
                float se = sb[base + n];
                acc = fmaf(se, wfac[warp * 16 + n], acc);
                sb[base + n] = se * zfac[warp * 16 + n];
            }
            wsS[warp * 16 + lane] = acc;
        }
        __syncwarp();

        // ---- scatter: triangular in 2 halves of 8 m, batched multireduce flush ----
        {
            const float* sb = sbuf + warp * 136;
            const float* ws = wsS + warp * 16;
            const size_t obase = (size_t)(smg * 512 + g) * 1024;

#pragma unroll
            for (int mh = 0; mh < 2; mh++) {
                float ax[8], ay[8];
#pragma unroll
                for (int i = 0; i < 8; i++) { ax[i] = 0.f; ay[i] = 0.f; }
#pragma unroll
                for (int i = 0; i < 8; i++) {
                    const int m = mh * 8 + i;
#pragma unroll
                    for (int n = 0; n <= m; n++) {
                        float C = sb[((m * (m + 1)) >> 1) + n];
                        ax[i] = fmaf(C, v16[n].x, ax[i]);
                        ay[i] = fmaf(C, v16[n].y, ay[i]);
                    }
                }
                // contrib (exclude dim0 = lane0's x slot), multireduce 8 values
                float c8[8];
#pragma unroll
                for (int i = 0; i < 8; i++)
                    c8[i] = (lane == 0) ? ay[i] * ay[i] : fmaf(ax[i], ax[i], ay[i] * ay[i]);
#pragma unroll
                for (int step = 0; step < 3; step++) {
                    const int mm = 1 << step;
                    const int h = 4 >> step;
                    const bool hi = (lane & mm) != 0;
#pragma unroll
                    for (int i = 0; i < h; i++) {
                        float sent = hi ? c8[i] : c8[i + h];
                        float recv = __shfl_xor_sync(0xffffffffu, sent, mm);
                        c8[i] = (hi ? c8[i + h] : c8[i]) + recv;
                    }
                }
                c8[0] += __shfl_xor_sync(0xffffffffu, c8[0], 8);
                c8[0] += __shfl_xor_sync(0xffffffffu, c8[0], 16);
                // lane owns value index brv3 (its m = mh*8 + brv3); compute scalars once
                float iw  = __fdividef(1.f, ws[mh * 8 + brv3]);
                float s2  = c8[0] * iw * iw;            // s2' scaled by 1/wsum^2
                float inv = rsqrtf(1.f - fminf(s2, 0.999f));
                float f   = iw * inv;
                // broadcast f, inv for all 8 m's (holder of value i is lane rev3(i))
#pragma unroll
                for (int i = 0; i < 8; i++) {
                    const int src = ((i & 1) << 2) | (i & 2) | ((i & 4) >> 2);  // rev3(i)
                    float fi  = __shfl_sync(0xffffffffu, f, src);
                    float ivi = __shfl_sync(0xffffffffu, inv, src);
                    float2 ov = make_float2(ax[i] * fi, ay[i] * fi);
                    if (lane == 0) ov.x = ivi;   // out[0] = lorenz of result
                    reinterpret_cast<float2*>(out + obase + (size_t)(mh * 8 + i) * 64)[lane] = ov;
                }
            }
        }
    }
}

// ---------------- launch ----------------
extern "C" void kernel_launch(void* const* d_in, const int* in_sizes, int n_in,
                              void* d_out, int out_size) {
    (void)in_sizes; (void)n_in; (void)out_size;
    const float* H    = (const float*)d_in[0];
    const float* mask = (const float*)d_in[2];
    const float* wq   = (const float*)d_in[3];
    const float* wk   = (const float*)d_in[4];
    const float* bq   = (const float*)d_in[5];
    const float* bk   = (const float*)d_in[6];
    const float* a    = (const float*)d_in[7];
    const float* c    = (const float*)d_in[8];
    float* out = (float*)d_out;

    const int MAIN_FLOATS = 2 * 8192 + 512 /* packed coefs */ + 8 + 8 + 64 + 64
                            + 8 * 136 + 128 + 128 + 128 + 136;
    const int MAIN_SMEM = MAIN_FLOATS * 4;   // ~74.5KB

    cudaFuncSetAttribute(main_kernel, cudaFuncAttributeMaxDynamicSharedMemorySize, MAIN_SMEM);

    gram_kernel<<<GNTILE, 320>>>(H);
    reduce_kernel<<<NPAIR, 256>>>();
    finalize_kernel<<<1, 256>>>(H, wq, wk, bq, bk, c);
    main_kernel<<<1024, 256, MAIN_SMEM>>>(H, mask, a, c, out);
}

// round 17
// speedup vs baseline: 1.1162x; 1.1162x over previous
#include <cuda_runtime.h>
#include <math.h>

// Problem constants (fixed by dataset)
#define NSAMP 8192
#define NND  (NSAMP * 64)        // 524288 (giant row length)
#define NPAIR 136                // 16*17/2 gram pairs
#define GTILE_COLS 512           // cols per gram block
#define GNTILE 1024              // 524288 / 512

// ---------------- device globals (scratch, statically allocated) ----------------
__device__ float g_partials[NPAIR][GNTILE];
__device__ float g_gram[NPAIR];
__device__ float g_coefQ[256];
__device__ float g_coefK[256];
__device__ float g_firstQ[16];
__device__ float g_firstK[16];
__device__ float g_uQ[64];
__device__ float g_uK[64];
__device__ float g_u2[2];        // ||u||^2 (dims 1..63) for q,k

typedef unsigned long long ull;

__device__ __forceinline__ float wreduce(float v) {
#pragma unroll
    for (int o = 16; o; o >>= 1) v += __shfl_xor_sync(0xffffffffu, v, o);
    return v;
}

__device__ __forceinline__ ull fma2(ull a, ull b, ull c) {
    ull d; asm("fma.rn.f32x2 %0, %1, %2, %3;" : "=l"(d) : "l"(a), "l"(b), "l"(c));
    return d;
}
__device__ __forceinline__ ull mul2(ull a, ull b) {
    ull d; asm("mul.rn.f32x2 %0, %1, %2;" : "=l"(d) : "l"(a), "l"(b));
    return d;
}
__device__ __forceinline__ ull pack2(float lo, float hi) {
    ull d; asm("mov.b64 %0, {%1, %2};" : "=l"(d) : "f"(lo), "f"(hi));
    return d;
}
__device__ __forceinline__ void unpack2(ull v, float& lo, float& hi) {
    asm("mov.b64 {%0, %1}, %2;" : "=f"(lo), "=f"(hi) : "l"(v));
}

// ---------------- Kernel 1: Gram partials, warp-per-4x4-block (10 warps) ----------------
extern "C" __global__ __launch_bounds__(320)
void gram_kernel(const float* __restrict__ H) {
    __shared__ float gt[16 * GTILE_COLS];   // 32KB
    const int b = blockIdx.x;
    const int tid = threadIdx.x;

    const float4* H4 = reinterpret_cast<const float4*>(H);
    for (int i = tid; i < 16 * (GTILE_COLS / 4); i += 320) {
        int s = i >> 7;
        int c4 = i & 127;
        reinterpret_cast<float4*>(gt + s * GTILE_COLS)[c4] =
            H4[(size_t)s * (NND / 4) + (size_t)b * (GTILE_COLS / 4) + c4];
    }
    __syncthreads();

    const int w = tid >> 5, lane = tid & 31;
    const int bi_arr[10] = {0, 1, 1, 2, 2, 2, 3, 3, 3, 3};
    const int bj_arr[10] = {0, 0, 1, 0, 1, 2, 0, 1, 2, 3};
    const int bi = bi_arr[w], bj = bj_arr[w];

    const float* A  = gt + (bi * 4) * GTILE_COLS + lane;
    const float* Bp = gt + (bj * 4) * GTILE_COLS + lane;
    float acc[16];
#pragma unroll
    for (int i = 0; i < 16; i++) acc[i] = 0.f;
#pragma unroll
    for (int c = 0; c < GTILE_COLS; c += 32) {
        float a0 = A[c], a1 = A[c + GTILE_COLS], a2 = A[c + 2 * GTILE_COLS], a3 = A[c + 3 * GTILE_COLS];
        float b0 = Bp[c], b1 = Bp[c + GTILE_COLS], b2 = Bp[c + 2 * GTILE_COLS], b3 = Bp[c + 3 * GTILE_COLS];
        acc[0]  = fmaf(a0, b0, acc[0]);   acc[1]  = fmaf(a0, b1, acc[1]);
        acc[2]  = fmaf(a0, b2, acc[2]);   acc[3]  = fmaf(a0, b3, acc[3]);
        acc[4]  = fmaf(a1, b0, acc[4]);   acc[5]  = fmaf(a1, b1, acc[5]);
        acc[6]  = fmaf(a1, b2, acc[6]);   acc[7]  = fmaf(a1, b3, acc[7]);
        acc[8]  = fmaf(a2, b0, acc[8]);   acc[9]  = fmaf(a2, b1, acc[9]);
        acc[10] = fmaf(a2, b2, acc[10]);  acc[11] = fmaf(a2, b3, acc[11]);
        acc[12] = fmaf(a3, b0, acc[12]);  acc[13] = fmaf(a3, b1, acc[13]);
        acc[14] = fmaf(a3, b2, acc[14]);  acc[15] = fmaf(a3, b3, acc[15]);
    }
#pragma unroll
    for (int ki = 0; ki < 4; ki++) {
#pragma unroll
        for (int kj = 0; kj < 4; kj++) {
            float v = wreduce(acc[ki * 4 + kj]);
            int s2 = bi * 4 + ki, s1 = bj * 4 + kj;
            if (lane == 0 && s1 <= s2)
                g_partials[(s2 * (s2 + 1)) / 2 + s1][b] = v;
        }
    }
}

// ---------------- Kernel 1b: parallel deterministic reduction of partials ----------------
extern "C" __global__ __launch_bounds__(256)
void reduce_kernel() {
    __shared__ float red[8];
    const int p = blockIdx.x;
    const int tid = threadIdx.x;
    const int w = tid >> 5, lane = tid & 31;
    float acc = 0.f;
    for (int k = tid; k < GNTILE; k += 256) acc += g_partials[p][k];
    acc = wreduce(acc);
    if (lane == 0) red[w] = acc;
    __syncthreads();
    if (w == 0) {
        float v = (lane < 8) ? red[lane] : 0.f;
        v = wreduce(v);
        if (lane == 0) g_gram[p] = v;
    }
}

// ---------------- Kernel 2: finalize small algebra ----------------
extern "C" __global__ __launch_bounds__(256, 1)
void finalize_kernel(const float* __restrict__ H,
                     const float* __restrict__ wq, const float* __restrict__ wk,
                     const float* __restrict__ bq, const float* __restrict__ bk,
                     const float* __restrict__ cin) {
    __shared__ float Gf[NPAIR];
    __shared__ float h0[16];
    __shared__ float scale[16];
    __shared__ float ubv[2], bnv[2];

    const int tid = threadIdx.x;
    const float cval = cin[0];
    const float Kv = 1.f / cval;
    const float sK = sqrtf(Kv);
    const float onep = 1.f + 1e-7f;

    if (tid < NPAIR) Gf[tid] = g_gram[tid];
    if (tid >= NPAIR && tid < NPAIR + 16) h0[tid - NPAIR] = H[(size_t)(tid - NPAIR) * NND];
    __syncthreads();

    auto GX = [&](int s1, int s2) -> float {
        int a = min(s1, s2), b = max(s1, s2);
        return Gf[(b * (b + 1)) / 2 + a] - h0[s1] * h0[s2];
    };

    if (tid < 16) {
        int s = tid;
        float yn = fmaxf(sqrtf(GX(s, s)), 1e-15f);
        float th = fmaxf(h0[s] / sK, onep);
        float ar = logf(th + sqrtf(fmaxf(th * th - 1.f, 1e-7f)));
        scale[s] = sK * ar / yn;
    }
    __syncthreads();

    if (tid < 32) {
        int r = tid & 15;
        const float* W = (tid < 16) ? wq : wk;
        float* coef = (tid < 16) ? g_coefQ : g_coefK;
        float* first = (tid < 16) ? g_firstQ : g_firstK;
        float Wp[16];
#pragma unroll
        for (int s = 0; s < 16; s++) Wp[s] = W[r * 16 + s] * scale[s];
        float xn2 = 0.f;
        for (int s = 0; s < 16; s++)
            for (int s2 = 0; s2 < 16; s2++)
                xn2 = fmaf(Wp[s] * Wp[s2], GX(s, s2), xn2);
        float xn = fmaxf(sqrtf(xn2), 1e-15f);
        float th = xn / sK;
        float cA = sK * sinhf(th) / xn;
        first[r] = sK * coshf(th);
#pragma unroll
        for (int s = 0; s < 16; s++) coef[r * 16 + s] = cA * Wp[s];
    }
    if (tid == 32 || tid == 33) {
        const float* b = (tid == 32) ? bq : bk;
        float s2 = 0.f;
        for (int j = 1; j < 64; j++) s2 += b[j] * b[j];
        float bn = fmaxf(sqrtf(s2), 1e-15f);
        float tb = fmaxf(b[0] / sK, onep);
        float ub = sK * logf(tb + sqrtf(fmaxf(tb * tb - 1.f, 1e-7f)));
        ubv[tid - 32] = ub;
        bnv[tid - 32] = bn;
        g_u2[tid - 32] = ub * ub;     // ||u||^2 = ub^2 since u = ub * y/||y||
    }
    __syncthreads();
    if (tid < 128) {
        int j = tid & 63;
        if (tid < 64) g_uQ[j] = (j == 0) ? 0.f : ubv[0] * bq[j] / bnv[0];
        else          g_uK[j] = (j == 0) ? 0.f : ubv[1] * bk[j] / bnv[1];
    }
}

// ---------------- Kernel 3: fused main, half-group CTAs (256 thr, 3 CTAs/SM) ----------------
extern "C" __global__ __launch_bounds__(256, 3)
void main_kernel(const float* __restrict__ H, const float* __restrict__ mask,
                 const float* __restrict__ ain, const float* __restrict__ cin,
                 float* __restrict__ out) {
    extern __shared__ float smem[];
    float* qm   = smem;                    // 8*1024
    float* km   = qm + 8192;               // 8*1024
    float* cQh  = km + 8192;               // 128 (this half's 8 q-coef rows)
    float* cKh  = cQh + 128;               // 128
    float* fQh  = cKh + 128;               // 8
    float* fKh  = fQh + 8;                 // 8
    float* uq   = fKh + 8;                 // 64
    float* uk   = uq + 64;                 // 64
    float* sbuf = uk + 64;                 // 8*136
    float* zfac = sbuf + 8 * 136;          // 8*16
    float* wfac = zfac + 128;              // 8*16
    float* wsS  = wfac + 128;              // 8*16
    float* maskS= wsS + 128;               // 136
    float* firsts = cQh;                   // OVERLAY (256 floats; coefs dead after phase 2)

    const int g = blockIdx.x >> 1;
    const int half = blockIdx.x & 1;
    const int tid = threadIdx.x;
    const int lane = tid & 31, warp = tid >> 5;
    const float cval = __ldg(cin);
    const float aval = __ldg(ain);
    const float Kv = 1.f / cval;
    const float sK = sqrtf(Kv);
    const float onep = 1.f + 1e-7f;

    if (tid < 128) cQh[tid] = g_coefQ[half * 128 + tid];
    else           cKh[tid - 128] = g_coefK[half * 128 + (tid - 128)];
    if (tid < 8)   { fQh[tid] = g_firstQ[half * 8 + tid]; fKh[tid] = g_firstK[half * 8 + tid]; }
    if (tid >= 8 && tid < 72)   uq[tid - 8] = g_uQ[tid - 8];
    if (tid >= 72 && tid < 136) uk[tid - 72] = g_uK[tid - 72];
    if (tid >= 120 && tid < 256) maskS[tid - 120] = __ldg(mask + (tid - 120));
    __syncthreads();

    // ---- phase 2: 16x16 mix -> 8 q,k r-rows (packed f32x2), H read via LDG ----
    {
        const float2* H2 = reinterpret_cast<const float2*>(H);
        float2* q2 = reinterpret_cast<float2*>(qm);
        float2* k2 = reinterpret_cast<float2*>(km);
#pragma unroll
        for (int cp = 0; cp < 2; cp++) {
            const int col = tid + cp * 256;     // float2 column in 0..511
            ull tv[16];
#pragma unroll
            for (int s = 0; s < 16; s++) {
                float2 v = __ldg(&H2[(size_t)(s * 512 + g) * 512 + col]);
                tv[s] = pack2(v.x, v.y);
            }
#pragma unroll
            for (int rl = 0; rl < 8; rl++) {
                const float4* cq4 = reinterpret_cast<const float4*>(cQh + rl * 16);
                const float4* ck4 = reinterpret_cast<const float4*>(cKh + rl * 16);
                ull aq = 0ull, ak = 0ull;
#pragma unroll
                for (int s4 = 0; s4 < 4; s4++) {
                    float4 cq = cq4[s4], ck = ck4[s4];
                    aq = fma2(pack2(cq.x, cq.x), tv[s4 * 4 + 0], aq);
                    aq = fma2(pack2(cq.y, cq.y), tv[s4 * 4 + 1], aq);
                    aq = fma2(pack2(cq.z, cq.z), tv[s4 * 4 + 2], aq);
                    aq = fma2(pack2(cq.w, cq.w), tv[s4 * 4 + 3], aq);
                    ak = fma2(pack2(ck.x, ck.x), tv[s4 * 4 + 0], ak);
                    ak = fma2(pack2(ck.y, ck.y), tv[s4 * 4 + 1], ak);
                    ak = fma2(pack2(ck.z, ck.z), tv[s4 * 4 + 2], ak);
                    ak = fma2(pack2(ck.w, ck.w), tv[s4 * 4 + 3], ak);
                }
                float qlo, qhi, klo, khi;
                unpack2(aq, qlo, qhi);
                unpack2(ak, klo, khi);
                if (g == 0 && col == 0) { qlo = fQh[rl]; klo = fKh[rl]; }  // expmap0 first column
                q2[rl * 512 + col] = make_float2(qlo, qhi);
                k2[rl * 512 + col] = make_float2(klo, khi);
            }
        }
    }
    __syncthreads();

    // ---- phase 3: mobius_add(b) + proj, thread-per-row, packed f32x2, closed form ----
    {
        const bool isq = tid < 128;
        float* X = isq ? qm : km;
        const float4* U4 = reinterpret_cast<const float4*>(isq ? uq : uk);
        const float u2 = isq ? g_u2[0] : g_u2[1];
        const int rloc = tid & 127;             // local sample (rloc>>4), tt (rloc&15)
        float* row = X + (rloc >> 4) * 1024 + (rloc & 15) * 64;
        float4* row4 = reinterpret_cast<float4*>(row);

        float x0 = 0.f;
        ull accY0 = 0ull, accY1 = 0ull, accD0 = 0ull, accD1 = 0ull;
#pragma unroll
        for (int jp = 0; jp < 16; jp++) {
            int p = (jp + lane) & 15;
            float4 xv = row4[p];
            float4 uv = U4[p];
            if (p == 0) x0 = xv.x;
            ull xa = pack2(xv.x, xv.y), xb = pack2(xv.z, xv.w);
            ull ua = pack2(uv.x, uv.y), ub = pack2(uv.z, uv.w);
            accY0 = fma2(xa, xa, accY0);
            accY1 = fma2(xb, xb, accY1);
            accD0 = fma2(xa, ua, accD0);
            accD1 = fma2(xb, ub, accD1);
        }
        float y0l, y0h, y1l, y1h, d0l, d0h, d1l, d1h;
        unpack2(accY0, y0l, y0h); unpack2(accY1, y1l, y1h);
        unpack2(accD0, d0l, d0h); unpack2(accD1, d1l, d1h);
        float yn2 = ((y0l + y0h) + (y1l + y1h)) - x0 * x0;   // exclude dim0
        float du  = (d0l + d0h) + (d1l + d1h);               // U[0]=0 -> exact

        float yn = fmaxf(sqrtf(fmaxf(yn2, 0.f)), 1e-15f);
        float alpha = du / (yn * sK);
        float fac = alpha * (sK - x0) / yn;
        float ux = du - fac * yn2;
        float first = ux / fmaxf(x0, 1e-7f);
        float w2 = fmaf(fac * fac, yn2, fmaf(-2.f * fac, du, u2));
        float md = fmaxf(w2 - first * first, 1e-7f);
        float nrm = fminf(sqrtf(md), 1e6f);
        float th = fmaxf(nrm / sK, 1e-15f);
        float ch = coshf(th);
        float shn = sinhf(th) / th;
        float A = fmaf(-shn, fac, ch);
        float B = shn;
        float r2 = fmaf(A * A, yn2, fmaf(2.f * A * B, du, B * B * u2));
        float o0 = sqrtf(fmaxf(Kv + r2, 1e-7f));

        const ull A2 = pack2(A, A), B2 = pack2(B, B);
#pragma unroll
        for (int jp = 0; jp < 16; jp++) {
            int p = (jp + lane) & 15;
            float4 xv = row4[p];
            float4 uv = U4[p];
            ull xa = pack2(xv.x, xv.y), xb = pack2(xv.z, xv.w);
            ull ua = pack2(uv.x, uv.y), ub = pack2(uv.z, uv.w);
            ull ra = fma2(A2, xa, mul2(B2, ua));
            ull rb = fma2(A2, xb, mul2(B2, ub));
            float4 rv;
            unpack2(ra, rv.x, rv.y);
            unpack2(rb, rv.z, rv.w);
            row4[p] = rv;
        }
        row[0] = o0;
        firsts[(isq ? 0 : 128) + rloc] = o0;     // overlay onto dead coef region
    }
    __syncthreads();

    // ---- phase 4: attention, warp per sample (8 warps, 8 samples) ----
    {
        const int smg = half * 8 + warp;         // global sample index
        const int brv = ((lane & 1) << 3) | ((lane & 2) << 1) | ((lane & 4) >> 1) | ((lane & 8) >> 3);
        const int brv3 = ((lane & 1) << 2) | (lane & 2) | ((lane & 4) >> 2);   // rev of low 3 bits
        const float2* hv2 = reinterpret_cast<const float2*>(H) + (size_t)(smg * 512 + g) * 512;

        // ---- dots: register-tiled 4x4 pair blocks; store RAW minkowski dot only ----
        {
            const float2* q2 = reinterpret_cast<const float2*>(qm + warp * 1024);
            const float2* k2 = reinterpret_cast<const float2*>(km + warp * 1024);
            const int pi = brv >> 2, pj = brv & 3;

            for (int bi = 0; bi < 4; bi++) {
                float2 qv[4];
#pragma unroll
                for (int i = 0; i < 4; i++) qv[i] = q2[(bi * 4 + i) * 32 + lane];
                for (int bj = 0; bj <= bi; bj++) {
                    float2 kv[4];
#pragma unroll
                    for (int j = 0; j < 4; j++) kv[j] = k2[(bj * 4 + j) * 32 + lane];
                    float acc[16];
#pragma unroll
                    for (int i = 0; i < 4; i++)
#pragma unroll
                        for (int j = 0; j < 4; j++)
                            acc[i * 4 + j] = fmaf(qv[i].x, kv[j].x, qv[i].y * kv[j].y);
#pragma unroll
                    for (int step = 0; step < 4; step++) {
                        const int mm = 1 << step;
                        const int h = 8 >> step;
                        const bool hi = (lane & mm) != 0;
#pragma unroll
                        for (int i = 0; i < h; i++) {
                            float sent = hi ? acc[i] : acc[i + h];
                            float recv = __shfl_xor_sync(0xffffffffu, sent, mm);
                            acc[i] = (hi ? acc[i + h] : acc[i]) + recv;
                        }
                    }
                    float S = acc[0] + __shfl_xor_sync(0xffffffffu, acc[0], 16);
                    int mt = bi * 4 + pi, nt = bj * 4 + pj;
                    if (lane < 16 && nt <= mt) {
                        int e = ((mt * (mt + 1)) >> 1) + nt;
                        float q0 = firsts[warp * 16 + mt];
                        float k0 = firsts[128 + warp * 16 + nt];
                        sbuf[warp * 136 + e] = fmaf(-2.f * q0, k0, S);   // raw mink dot
                    }
                }
            }
        }
        __syncwarp();

        // ---- batched exp pass: all 32 lanes, 5 iters, pipelined MUFU ----
        for (int e = lane; e < 136; e += 32) {
            float mdot = sbuf[warp * 136 + e];
            float thv = fmaxf(-mdot * cval, onep);
            float ar = __logf(thv + sqrtf(fmaxf(thv * thv - 1.f, 1e-7f)));
            float sq = fminf(Kv * ar * ar, 50.f);
            sbuf[warp * 136 + e] = __expf(fmaf(-aval, sq, maskS[e] - cval));
        }
        __syncwarp();

        // ---- lorenz factors from v16 (kept in regs through scatter) ----
        float2 v16[16];
#pragma unroll
        for (int n = 0; n < 16; n++) v16[n] = __ldg(&hv2[n * 32 + lane]);
        {
            float h0b = 0.f;
            if (lane < 16) h0b = __ldg(H + (size_t)(smg * 512 + g) * 1024 + brv * 64);
            float acc[16];
#pragma unroll
            for (int n = 0; n < 16; n++)
                acc[n] = fmaf(v16[n].x, v16[n].x, v16[n].y * v16[n].y);
#pragma unroll
            for (int step = 0; step < 4; step++) {
                const int mm = 1 << step;
                const int h = 8 >> step;
                const bool hi = (lane & mm) != 0;
#pragma unroll
                for (int i = 0; i < h; i++) {
                    float sent = hi ? acc[i] : acc[i + h];
                    float recv = __shfl_xor_sync(0xffffffffu, sent, mm);
                    acc[i] = (hi ? acc[i + h] : acc[i]) + recv;
                }
            }
            float S = acc[0] + __shfl_xor_sync(0xffffffffu, acc[0], 16);
            if (lane < 16) {
                float iv = 1.f / h0b;
                float svn = (S - h0b * h0b) * iv * iv;
                zfac[warp * 16 + brv] = iv;
                wfac[warp * 16 + brv] = rsqrtf(1.f - fminf(svn, 0.9f));
            }
        }
        __syncwarp();

        // ---- ssum per m (static triangular) + fold factors ----
        if (lane < 16) {
            const float* sbt = sbuf + warp * 136 + ((lane * (lane + 1)) >> 1);
            float acc = 0.f;
            for (int j = 0; j <= lane; j++) acc += sbt[j];
            float f = wfac[warp * 16 + lane] / acc;    // lamb / ssum
            wfac[warp * 16 + lane] = f;
            zfac[warp * 16 + lane] = f * zfac[warp * 16 + lane];
        }
        __syncwarp();

        // ---- wsum + coefficient matrix in place (lane m handles row m) ----
        if (lane < 16) {
            float* sb = sbuf + warp * 136;
            int base = (lane * (lane + 1)) >> 1;
            float acc = 0.f;
            for (int n = 0; n <= lane; n++) {
                float se = sb[base + n];
                acc = fmaf(se, wfac[warp * 16 + n], acc);
                sb[base + n] = se * zfac[warp * 16 + n];
            }
            wsS[warp * 16 + lane] = acc;
        }
        __syncwarp();

        // ---- scatter: triangular in 2 halves of 8 m, batched multireduce flush ----
        {
            const float* sb = sbuf + warp * 136;
            const float* ws = wsS + warp * 16;
            const size_t obase = (size_t)(smg * 512 + g) * 1024;

#pragma unroll
            for (int mh = 0; mh < 2; mh++) {
                float ax[8], ay[8];
#pragma unroll
                for (int i = 0; i < 8; i++) { ax[i] = 0.f; ay[i] = 0.f; }
#pragma unroll
                for (int i = 0; i < 8; i++) {
                    const int m = mh * 8 + i;
#pragma unroll
                    for (int n = 0; n <= m; n++) {
                        float C = sb[((m * (m + 1)) >> 1) + n];
                        ax[i] = fmaf(C, v16[n].x, ax[i]);
                        ay[i] = fmaf(C, v16[n].y, ay[i]);
                    }
                }
                // contrib (exclude dim0 = lane0's x slot), multireduce 8 values
                float c8[8];
#pragma unroll
                for (int i = 0; i < 8; i++)
                    c8[i] = (lane == 0) ? ay[i] * ay[i] : fmaf(ax[i], ax[i], ay[i] * ay[i]);
#pragma unroll
                for (int step = 0; step < 3; step++) {
                    const int mm = 1 << step;
                    const int h = 4 >> step;
                    const bool hi = (lane & mm) != 0;
#pragma unroll
                    for (int i = 0; i < h; i++) {
                        float sent = hi ? c8[i] : c8[i + h];
                        float recv = __shfl_xor_sync(0xffffffffu, sent, mm);
                        c8[i] = (hi ? c8[i + h] : c8[i]) + recv;
                    }
                }
                c8[0] += __shfl_xor_sync(0xffffffffu, c8[0], 8);
                c8[0] += __shfl_xor_sync(0xffffffffu, c8[0], 16);
                // lane owns value index brv3 (its m = mh*8 + brv3); compute scalars once
                float iw  = __fdividef(1.f, ws[mh * 8 + brv3]);
                float s2  = c8[0] * iw * iw;            // s2' scaled by 1/wsum^2
                float inv = rsqrtf(1.f - fminf(s2, 0.999f));
                float f   = iw * inv;
                // broadcast f, inv for all 8 m's (holder of value i is lane rev3(i))
#pragma unroll
                for (int i = 0; i < 8; i++) {
                    const int src = ((i & 1) << 2) | (i & 2) | ((i & 4) >> 2);  // rev3(i)
                    float fi  = __shfl_sync(0xffffffffu, f, src);
                    float ivi = __shfl_sync(0xffffffffu, inv, src);
                    float2 ov = make_float2(ax[i] * fi, ay[i] * fi);
                    if (lane == 0) ov.x = ivi;   // out[0] = lorenz of result
                    reinterpret_cast<float2*>(out + obase + (size_t)(mh * 8 + i) * 64)[lane] = ov;
                }
            }
        }
    }
}

// ---------------- launch ----------------
extern "C" void kernel_launch(void* const* d_in, const int* in_sizes, int n_in,
                              void* d_out, int out_size) {
    (void)in_sizes; (void)n_in; (void)out_size;
    const float* H    = (const float*)d_in[0];
    const float* mask = (const float*)d_in[2];
    const float* wq   = (const float*)d_in[3];
    const float* wk   = (const float*)d_in[4];
    const float* bq   = (const float*)d_in[5];
    const float* bk   = (const float*)d_in[6];
    const float* a    = (const float*)d_in[7];
    const float* c    = (const float*)d_in[8];
    float* out = (float*)d_out;

    const int MAIN_FLOATS = 2 * 8192 + 128 + 128 + 8 + 8 + 64 + 64
                            + 8 * 136 + 128 + 128 + 128 + 136;
    const int MAIN_SMEM = MAIN_FLOATS * 4;   // ~73.5KB

    cudaFuncSetAttribute(main_kernel, cudaFuncAttributeMaxDynamicSharedMemorySize, MAIN_SMEM);

    gram_kernel<<<GNTILE, 320>>>(H);
    reduce_kernel<<<NPAIR, 256>>>();
    finalize_kernel<<<1, 256>>>(H, wq, wk, bq, bk, c);
    main_kernel<<<1024, 256, MAIN_SMEM>>>(H, mask, a, c, out);
}